// round 1
// baseline (speedup 1.0000x reference)
#include <cuda_runtime.h>
#include <math.h>

// Problem constants
#define Bq   16
#define Tq   2048
#define Dq   512
#define Hq   16
#define HDq  32
#define Fq   2048
#define Lq   4
#define Cq   10
#define BTq  (Bq * Tq)          // 32768 rows

// ---------------------------------------------------------------------------
// Static device scratch (allocation-free rule: __device__ globals only)
// ---------------------------------------------------------------------------
__device__ float g_x  [BTq * Dq];   // 64 MB  residual stream
__device__ float g_tmp[BTq * Dq];   // 64 MB  attn_out / ffn activation
__device__ float g_ff [BTq * Fq];   // 256 MB ffn intermediate
__device__ float g_rx_sum[Lq];
__device__ float g_ry_cos[Lq];

// ---------------------------------------------------------------------------
// Per-layer scalar reductions: sum(rx_params[l]), cos(sum(ry_params[l]))
// ---------------------------------------------------------------------------
__global__ void scalars_kernel(const float* __restrict__ rx,
                               const float* __restrict__ ry)
{
    int l = blockIdx.x;                 // Lq blocks
    __shared__ float red[512];
    int tid = threadIdx.x;              // 512 threads
    red[tid] = ry[l * Dq + tid];
    __syncthreads();
    for (int s = 256; s; s >>= 1) {
        if (tid < s) red[tid] += red[tid + s];
        __syncthreads();
    }
    if (tid == 0) {
        g_ry_cos[l] = cosf(red[0]);
        float s = 0.f;
        #pragma unroll
        for (int i = 0; i < HDq; i++) s += rx[l * HDq + i];
        g_rx_sum[l] = s;
    }
}

// ---------------------------------------------------------------------------
// Embedding gather + sinusoidal positional encoding
// x[b,t,d] = emb[tokens[b,t], d] + PE(t, d)
// ---------------------------------------------------------------------------
__global__ void embed_kernel(const int* __restrict__ tokens,
                             const float* __restrict__ emb)
{
    int idx = blockIdx.x * blockDim.x + threadIdx.x;
    if (idx >= BTq * Dq) return;
    int d  = idx & (Dq - 1);
    int bt = idx >> 9;                  // / Dq
    int t  = bt & (Tq - 1);
    int tok = tokens[bt];
    // div = exp((d & ~1) * (-ln(10000)/D)); even d -> sin, odd d -> cos
    float div = expf((float)(d & ~1) * (-9.210340371976184f / (float)Dq));
    float ang = (float)t * div;
    float pe  = (d & 1) ? cosf(ang) : sinf(ang);
    g_x[idx] = emb[(size_t)tok * Dq + d] + pe;
}

// ---------------------------------------------------------------------------
// Fused: LN1 -> cos(h + rx_sum) -> per-position head-Gram attention -> out
// One CTA (256 threads) per (b,t) row. D = 512.
// scores[h,g] = <q_h, q_g> / sqrt(HD)   (16x16, per position)
// out[h,d]    = sum_g softmax(scores)[h,g] * q[g,d]
// ---------------------------------------------------------------------------
__global__ __launch_bounds__(256)
void attn_kernel(const float* __restrict__ xin,
                 const float* __restrict__ lns,
                 const float* __restrict__ lnb,
                 const float* __restrict__ rx_sum_p,
                 float* __restrict__ out)
{
    int row = blockIdx.x;
    const float* xr = xin + (size_t)row * Dq;
    int tid = threadIdx.x;

    float v0 = xr[tid];
    float v1 = xr[tid + 256];

    // block reduce: sum and sum of squares
    float sum = v0 + v1;
    float sq  = v0 * v0 + v1 * v1;
    #pragma unroll
    for (int o = 16; o; o >>= 1) {
        sum += __shfl_xor_sync(0xFFFFFFFFu, sum, o);
        sq  += __shfl_xor_sync(0xFFFFFFFFu, sq,  o);
    }
    __shared__ float wsum[8], wsq[8];
    int wid = tid >> 5, lid = tid & 31;
    if (lid == 0) { wsum[wid] = sum; wsq[wid] = sq; }
    __syncthreads();
    if (tid == 0) {
        float s = 0.f, q2 = 0.f;
        #pragma unroll
        for (int i = 0; i < 8; i++) { s += wsum[i]; q2 += wsq[i]; }
        wsum[0] = s; wsq[0] = q2;
    }
    __syncthreads();
    float mu  = wsum[0] * (1.0f / Dq);
    float var = wsq[0] * (1.0f / Dq) - mu * mu;
    float rs  = rsqrtf(var + 1e-5f);
    float rxs = *rx_sum_p;

    __shared__ float q[Dq];
    q[tid]       = cosf((v0 - mu) * rs * lns[tid]       + lnb[tid]       + rxs);
    q[tid + 256] = cosf((v1 - mu) * rs * lns[tid + 256] + lnb[tid + 256] + rxs);
    __syncthreads();

    // scores: thread (h,g) with h = tid>>4, g = tid&15
    int h = tid >> 4, g = tid & 15;
    const float* qh_ = q + h * HDq;
    const float* qg_ = q + g * HDq;
    float sc = 0.f;
    #pragma unroll
    for (int d = 0; d < HDq; d++) sc += qh_[d] * qg_[d];
    sc *= 0.17677669529663687f;          // 1/sqrt(32)

    // softmax over g within 16-lane groups
    float mx = sc;
    #pragma unroll
    for (int o = 8; o; o >>= 1) mx = fmaxf(mx, __shfl_xor_sync(0xFFFFFFFFu, mx, o));
    float e = expf(sc - mx);
    float se = e;
    #pragma unroll
    for (int o = 8; o; o >>= 1) se += __shfl_xor_sync(0xFFFFFFFFu, se, o);

    __shared__ float a[Hq * Hq];
    a[tid] = e / se;
    __syncthreads();

    // out: element e0 = tid, e1 = tid + 256 ; element = h*32 + d
    int h0 = tid >> 5, d0 = tid & 31;
    int h1 = (tid + 256) >> 5;
    float o0 = 0.f, o1 = 0.f;
    #pragma unroll
    for (int gg = 0; gg < Hq; gg++) {
        float qv = q[gg * HDq + d0];
        o0 += a[h0 * Hq + gg] * qv;
        o1 += a[h1 * Hq + gg] * qv;
    }
    out[(size_t)row * Dq + tid]       = o0;
    out[(size_t)row * Dq + tid + 256] = o1;
}

// ---------------------------------------------------------------------------
// Fused: LN2 -> ry_cos * cos(h2)  (per-row, 256 threads)
// ---------------------------------------------------------------------------
__global__ __launch_bounds__(256)
void ffact_kernel(const float* __restrict__ xin,
                  const float* __restrict__ lns,
                  const float* __restrict__ lnb,
                  const float* __restrict__ ry_cos_p,
                  float* __restrict__ out)
{
    int row = blockIdx.x;
    const float* xr = xin + (size_t)row * Dq;
    int tid = threadIdx.x;

    float v0 = xr[tid];
    float v1 = xr[tid + 256];
    float sum = v0 + v1;
    float sq  = v0 * v0 + v1 * v1;
    #pragma unroll
    for (int o = 16; o; o >>= 1) {
        sum += __shfl_xor_sync(0xFFFFFFFFu, sum, o);
        sq  += __shfl_xor_sync(0xFFFFFFFFu, sq,  o);
    }
    __shared__ float wsum[8], wsq[8];
    int wid = tid >> 5, lid = tid & 31;
    if (lid == 0) { wsum[wid] = sum; wsq[wid] = sq; }
    __syncthreads();
    if (tid == 0) {
        float s = 0.f, q2 = 0.f;
        #pragma unroll
        for (int i = 0; i < 8; i++) { s += wsum[i]; q2 += wsq[i]; }
        wsum[0] = s; wsq[0] = q2;
    }
    __syncthreads();
    float mu  = wsum[0] * (1.0f / Dq);
    float var = wsq[0] * (1.0f / Dq) - mu * mu;
    float rs  = rsqrtf(var + 1e-5f);
    float ryc = *ry_cos_p;

    float* orow = out + (size_t)row * Dq;
    orow[tid]       = ryc * cosf((v0 - mu) * rs * lns[tid]       + lnb[tid]);
    orow[tid + 256] = ryc * cosf((v1 - mu) * rs * lns[tid + 256] + lnb[tid + 256]);
}

// ---------------------------------------------------------------------------
// Tiled fp32 GEMM, NT layout: C[m,n] (+|relu)= sum_k A[m,k] * W[n,k]
// BM=BN=128, BK=8, 256 threads, 8x8 microtiles.
// M % 128 == 0, N % 128 == 0, K % 8 == 0 always hold here (no bounds checks).
// ---------------------------------------------------------------------------
template <bool RELU, bool ACCUM>
__global__ __launch_bounds__(256)
void gemm_nt(const float* __restrict__ A,
             const float* __restrict__ W,
             float* __restrict__ C,
             int M, int N, int K)
{
    constexpr int BM = 128, BN = 128, BK = 8;
    __shared__ float As[BK][BM];
    __shared__ float Bs[BK][BN];

    const int bm = blockIdx.y * BM;
    const int bn = blockIdx.x * BN;
    const int tid = threadIdx.x;

    const int tm = (tid / 16) * 8;      // 0..120
    const int tn = (tid % 16) * 8;      // 0..120

    // loader mapping: 256 threads load 128x8 tile; 2 threads per row, float4 each
    const int lrow = tid >> 1;          // 0..127
    const int lk   = (tid & 1) * 4;     // 0 or 4

    const float* Ap = A + (size_t)(bm + lrow) * K + lk;
    const float* Wp = W + (size_t)(bn + lrow) * K + lk;

    float acc[8][8] = {};

    for (int k0 = 0; k0 < K; k0 += BK) {
        float4 av = *(const float4*)(Ap + k0);
        float4 wv = *(const float4*)(Wp + k0);
        __syncthreads();
        As[lk + 0][lrow] = av.x; As[lk + 1][lrow] = av.y;
        As[lk + 2][lrow] = av.z; As[lk + 3][lrow] = av.w;
        Bs[lk + 0][lrow] = wv.x; Bs[lk + 1][lrow] = wv.y;
        Bs[lk + 2][lrow] = wv.z; Bs[lk + 3][lrow] = wv.w;
        __syncthreads();

        #pragma unroll
        for (int k = 0; k < BK; k++) {
            float4 ra0 = *(const float4*)&As[k][tm];
            float4 ra1 = *(const float4*)&As[k][tm + 4];
            float4 rb0 = *(const float4*)&Bs[k][tn];
            float4 rb1 = *(const float4*)&Bs[k][tn + 4];
            float a[8] = {ra0.x, ra0.y, ra0.z, ra0.w, ra1.x, ra1.y, ra1.z, ra1.w};
            float b[8] = {rb0.x, rb0.y, rb0.z, rb0.w, rb1.x, rb1.y, rb1.z, rb1.w};
            #pragma unroll
            for (int i = 0; i < 8; i++)
                #pragma unroll
                for (int j = 0; j < 8; j++)
                    acc[i][j] += a[i] * b[j];
        }
    }

    #pragma unroll
    for (int i = 0; i < 8; i++) {
        float* cp = C + (size_t)(bm + tm + i) * N + bn + tn;
        #pragma unroll
        for (int j = 0; j < 8; j++) {
            float v = acc[i][j];
            if (RELU)  v = fmaxf(v, 0.f);
            if (ACCUM) v += cp[j];
            cp[j] = v;
        }
    }
}

// ---------------------------------------------------------------------------
// Mean pool over T then tiny classifier: out[b,c] = pooled_b . clf_w[c] + clf_b[c]
// One CTA per batch element.
// ---------------------------------------------------------------------------
__global__ __launch_bounds__(256)
void pool_clf_kernel(const float* __restrict__ clf_w,
                     const float* __restrict__ clf_b,
                     float* __restrict__ out)
{
    int b = blockIdx.x;
    int tid = threadIdx.x;
    __shared__ float pooled[Dq];
    const float* xb = g_x + (size_t)b * Tq * Dq;
    float s0 = 0.f, s1 = 0.f;
    for (int t = 0; t < Tq; t++) {
        s0 += xb[(size_t)t * Dq + tid];
        s1 += xb[(size_t)t * Dq + tid + 256];
    }
    pooled[tid]       = s0 * (1.0f / Tq);
    pooled[tid + 256] = s1 * (1.0f / Tq);
    __syncthreads();
    if (tid < Cq) {
        float acc = clf_b[tid];
        const float* wr = clf_w + (size_t)tid * Dq;
        for (int d = 0; d < Dq; d++) acc += pooled[d] * wr[d];
        out[b * Cq + tid] = acc;
    }
}

// ---------------------------------------------------------------------------
// Launch
// ---------------------------------------------------------------------------
extern "C" void kernel_launch(void* const* d_in, const int* in_sizes, int n_in,
                              void* d_out, int out_size)
{
    (void)in_sizes; (void)n_in; (void)out_size;

    const int*   tokens = (const int*)  d_in[0];
    const float* emb    = (const float*)d_in[1];
    const float* ln1_s  = (const float*)d_in[2];
    const float* ln1_b  = (const float*)d_in[3];
    const float* ln2_s  = (const float*)d_in[4];
    const float* ln2_b  = (const float*)d_in[5];
    const float* rx     = (const float*)d_in[6];
    const float* ry     = (const float*)d_in[7];
    const float* proj_w = (const float*)d_in[8];
    const float* lin1_w = (const float*)d_in[9];
    const float* lin2_w = (const float*)d_in[10];
    const float* clf_w  = (const float*)d_in[11];
    const float* clf_b  = (const float*)d_in[12];
    float* out = (float*)d_out;

    float *px, *ptmp, *pff, *prx, *pryc;
    cudaGetSymbolAddress((void**)&px,   g_x);
    cudaGetSymbolAddress((void**)&ptmp, g_tmp);
    cudaGetSymbolAddress((void**)&pff,  g_ff);
    cudaGetSymbolAddress((void**)&prx,  g_rx_sum);
    cudaGetSymbolAddress((void**)&pryc, g_ry_cos);

    scalars_kernel<<<Lq, 512>>>(rx, ry);
    embed_kernel<<<(BTq * Dq + 255) / 256, 256>>>(tokens, emb);

    for (int l = 0; l < Lq; l++) {
        // attention block
        attn_kernel<<<BTq, 256>>>(px, ln1_s + l * Dq, ln1_b + l * Dq,
                                  prx + l, ptmp);
        gemm_nt<false, true><<<dim3(Dq / 128, BTq / 128), 256>>>(
            ptmp, proj_w + (size_t)l * Dq * Dq, px, BTq, Dq, Dq);
        // ffn block
        ffact_kernel<<<BTq, 256>>>(px, ln2_s + l * Dq, ln2_b + l * Dq,
                                   pryc + l, ptmp);
        gemm_nt<true, false><<<dim3(Fq / 128, BTq / 128), 256>>>(
            ptmp, lin1_w + (size_t)l * Fq * Dq, pff, BTq, Fq, Dq);
        gemm_nt<false, true><<<dim3(Dq / 128, BTq / 128), 256>>>(
            pff, lin2_w + (size_t)l * Dq * Fq, px, BTq, Dq, Fq);
    }

    pool_clf_kernel<<<Bq, 256>>>(clf_w, clf_b, out);
}

// round 3
// speedup vs baseline: 1.9427x; 1.9427x over previous
#include <cuda_runtime.h>
#include <cuda_bf16.h>
#include <math.h>
#include <stdint.h>

// Problem constants
#define Bq   16
#define Tq   2048
#define Dq   512
#define Hq   16
#define HDq  32
#define Fq   2048
#define Lq   4
#define Cq   10
#define BTq  (Bq * Tq)          // 32768 rows

// ---------------------------------------------------------------------------
// Static device scratch
// ---------------------------------------------------------------------------
__device__ float         g_x  [BTq * Dq];        // fp32 residual stream
__device__ __nv_bfloat16 g_ah [BTq * Dq];        // activation hi
__device__ __nv_bfloat16 g_al [BTq * Dq];        // activation lo
__device__ __nv_bfloat16 g_ffh[BTq * Fq];        // ffn intermediate hi
__device__ __nv_bfloat16 g_ffl[BTq * Fq];        // ffn intermediate lo
__device__ __nv_bfloat16 g_wph[Lq * Dq * Dq], g_wpl[Lq * Dq * Dq];
__device__ __nv_bfloat16 g_w1h[Lq * Fq * Dq], g_w1l[Lq * Fq * Dq];
__device__ __nv_bfloat16 g_w2h[Lq * Dq * Fq], g_w2l[Lq * Dq * Fq];
__device__ float         g_pp [Bq * 16 * Dq];    // pooling partials
__device__ float         g_rx_sum[Lq];
__device__ float         g_ry_cos[Lq];

// ---------------------------------------------------------------------------
// Helpers
// ---------------------------------------------------------------------------
__device__ __forceinline__ uint32_t smem_u32(const void* p) {
    uint32_t a;
    asm("{ .reg .u64 t; cvta.to.shared.u64 t, %1; cvt.u32.u64 %0, t; }"
        : "=r"(a) : "l"(p));
    return a;
}

__device__ __forceinline__ void cp_async16(uint32_t dst, const void* src) {
    asm volatile("cp.async.cg.shared.global [%0], [%1], 16;"
                 :: "r"(dst), "l"(src) : "memory");
}
#define CP_COMMIT()  asm volatile("cp.async.commit_group;" ::: "memory")
#define CP_WAIT(n)   asm volatile("cp.async.wait_group %0;" :: "n"(n) : "memory")

__device__ __forceinline__ void ldsm4(uint32_t* r, uint32_t addr) {
    asm volatile("ldmatrix.sync.aligned.m8n8.x4.shared.b16 {%0,%1,%2,%3}, [%4];"
                 : "=r"(r[0]), "=r"(r[1]), "=r"(r[2]), "=r"(r[3]) : "r"(addr));
}

__device__ __forceinline__ void mma16816(float* d, const uint32_t* a,
                                         const uint32_t* b) {
    asm volatile(
        "mma.sync.aligned.m16n8k16.row.col.f32.bf16.bf16.f32 "
        "{%0,%1,%2,%3}, {%4,%5,%6,%7}, {%8,%9}, {%0,%1,%2,%3};"
        : "+f"(d[0]), "+f"(d[1]), "+f"(d[2]), "+f"(d[3])
        : "r"(a[0]), "r"(a[1]), "r"(a[2]), "r"(a[3]), "r"(b[0]), "r"(b[1]));
}

__device__ __forceinline__ void split2(float v, __nv_bfloat16& h, __nv_bfloat16& l) {
    h = __float2bfloat16(v);
    l = __float2bfloat16(v - __bfloat162float(h));
}

// ---------------------------------------------------------------------------
// Split-bf16 tensor-core GEMM (mma.sync):
//   C[m,n] = sum_k A[m,k] * B[n,k],   A = Ah+Al, B = Bh+Bl (bf16 hi/lo)
//   D = Ah*Bh + Ah*Bl + Al*Bh  (fp32 accum, ~2^-18 accurate)
// CTA tile 128x128, BK=32, 256 threads (4 m-warps x 2 n-warps, 32x64 per warp)
// 3-stage cp.async pipeline. SMEM rows padded to 80B (conflict-free ldmatrix).
// EPI 0: C += D (fp32 residual).  EPI 1: relu(D) -> split -> (Oh, Ol).
// ---------------------------------------------------------------------------
#define TILE_B   10240              // 128 rows * 80 bytes
#define STAGE_B  (4 * TILE_B)       // Ah, Al, Bh, Bl
#define GEMM_SMEM_BYTES (3 * STAGE_B)

template <int EPI>
__global__ __launch_bounds__(256, 1)
void gemm_mma(const __nv_bfloat16* __restrict__ Ah, const __nv_bfloat16* __restrict__ Al,
              const __nv_bfloat16* __restrict__ Bh, const __nv_bfloat16* __restrict__ Bl,
              float* __restrict__ C,
              __nv_bfloat16* __restrict__ Oh, __nv_bfloat16* __restrict__ Ol,
              int N, int K)
{
    extern __shared__ char smem[];
    const uint32_t sbase = smem_u32(smem);
    const int tid  = threadIdx.x;
    const int wid  = tid >> 5;
    const int lane = tid & 31;
    const int wm   = wid & 3;          // m-warp: rows wm*32 .. +31
    const int wn   = wid >> 2;         // n-warp: cols wn*64 .. +63

    const int bm = blockIdx.y * 128;
    const int bn = blockIdx.x * 128;

    const __nv_bfloat16* gsrc[4] = { Ah, Al, Bh, Bl };
    const int rowbase[4] = { bm, bm, bn, bn };

    // stage loader: 4 tiles x 128 rows x 32 bf16; 16B per cp.async
    auto load_stage = [&](int s, int kiter) {
        const uint32_t st = sbase + s * STAGE_B;
        #pragma unroll
        for (int t = 0; t < 4; ++t) {
            #pragma unroll
            for (int half = 0; half < 2; ++half) {
                int idx = tid + half * 256;      // 0..511
                int row = idx >> 2;
                int c   = idx & 3;
                const __nv_bfloat16* src =
                    gsrc[t] + (size_t)(rowbase[t] + row) * K + kiter * 32 + c * 8;
                cp_async16(st + t * TILE_B + row * 80 + c * 16, src);
            }
        }
    };

    float acc[2][8][4];
    #pragma unroll
    for (int i = 0; i < 2; ++i)
        #pragma unroll
        for (int j = 0; j < 8; ++j)
            #pragma unroll
            for (int k = 0; k < 4; ++k) acc[i][j][k] = 0.f;

    const int nc = K >> 5;             // K / 32

    load_stage(0, 0); CP_COMMIT();
    load_stage(1, 1); CP_COMMIT();

    const uint32_t lrow16 = (uint32_t)(lane & 15) * 80;   // row within frag
    const uint32_t khalf  = (uint32_t)(lane >> 4) * 16;   // k-half 16B

    for (int i = 0; i < nc; ++i) {
        CP_WAIT(1);
        __syncthreads();

        const uint32_t st = sbase + (uint32_t)(i % 3) * STAGE_B;
        #pragma unroll
        for (int ks = 0; ks < 2; ++ks) {
            const uint32_t kb = ks * 32 + khalf;

            uint32_t a_h[2][4], a_l[2][4];
            #pragma unroll
            for (int mf = 0; mf < 2; ++mf) {
                uint32_t ad = st + (uint32_t)(wm * 32 + mf * 16) * 80 + lrow16 + kb;
                ldsm4(a_h[mf], ad);
                ldsm4(a_l[mf], ad + TILE_B);
            }
            uint32_t b_h[8][2], b_l[8][2];
            #pragma unroll
            for (int nq = 0; nq < 4; ++nq) {
                uint32_t bd = st + 2 * TILE_B +
                              (uint32_t)(wn * 64 + nq * 16) * 80 + lrow16 + kb;
                uint32_t r[4];
                ldsm4(r, bd);
                b_h[nq * 2][0] = r[0]; b_h[nq * 2][1] = r[2];
                b_h[nq * 2 + 1][0] = r[1]; b_h[nq * 2 + 1][1] = r[3];
                ldsm4(r, bd + TILE_B);
                b_l[nq * 2][0] = r[0]; b_l[nq * 2][1] = r[2];
                b_l[nq * 2 + 1][0] = r[1]; b_l[nq * 2 + 1][1] = r[3];
            }
            #pragma unroll
            for (int mf = 0; mf < 2; ++mf)
                #pragma unroll
                for (int nf = 0; nf < 8; ++nf) {
                    mma16816(acc[mf][nf], a_h[mf], b_h[nf]);
                    mma16816(acc[mf][nf], a_h[mf], b_l[nf]);
                    mma16816(acc[mf][nf], a_l[mf], b_h[nf]);
                }
        }

        if (i + 2 < nc) load_stage((i + 2) % 3, i + 2);
        CP_COMMIT();
    }

    // epilogue: thread owns rows r0, r0+8; cols col, col+1 per (mf, nf)
    #pragma unroll
    for (int mf = 0; mf < 2; ++mf) {
        const int r0 = bm + wm * 32 + mf * 16 + (lane >> 2);
        #pragma unroll
        for (int nf = 0; nf < 8; ++nf) {
            const int col = bn + wn * 64 + nf * 8 + (lane & 3) * 2;
            float* d = acc[mf][nf];
            if (EPI == 0) {
                float* c0 = C + (size_t)r0 * N + col;
                float* c1 = C + (size_t)(r0 + 8) * N + col;
                c0[0] += d[0]; c0[1] += d[1];
                c1[0] += d[2]; c1[1] += d[3];
            } else {
                #pragma unroll
                for (int rr = 0; rr < 2; ++rr) {
                    size_t off = (size_t)(r0 + rr * 8) * N + col;
                    float v0 = fmaxf(d[rr * 2 + 0], 0.f);
                    float v1 = fmaxf(d[rr * 2 + 1], 0.f);
                    __nv_bfloat16 h0, l0, h1, l1;
                    split2(v0, h0, l0);
                    split2(v1, h1, l1);
                    *(__nv_bfloat162*)(Oh + off) = __nv_bfloat162(h0, h1);
                    *(__nv_bfloat162*)(Ol + off) = __nv_bfloat162(l0, l1);
                }
            }
        }
    }
}

// ---------------------------------------------------------------------------
// Per-layer scalar reductions
// ---------------------------------------------------------------------------
__global__ void scalars_kernel(const float* __restrict__ rx,
                               const float* __restrict__ ry)
{
    int l = blockIdx.x;
    __shared__ float red[512];
    int tid = threadIdx.x;
    red[tid] = ry[l * Dq + tid];
    __syncthreads();
    for (int s = 256; s; s >>= 1) {
        if (tid < s) red[tid] += red[tid + s];
        __syncthreads();
    }
    if (tid == 0) {
        g_ry_cos[l] = cosf(red[0]);
        float s = 0.f;
        #pragma unroll
        for (int i = 0; i < HDq; i++) s += rx[l * HDq + i];
        g_rx_sum[l] = s;
    }
}

// ---------------------------------------------------------------------------
// Weight hi/lo split conversion
// ---------------------------------------------------------------------------
__global__ void convert_kernel(const float* __restrict__ src,
                               __nv_bfloat16* __restrict__ hi,
                               __nv_bfloat16* __restrict__ lo, int n)
{
    int i = blockIdx.x * blockDim.x + threadIdx.x;
    if (i >= n) return;
    __nv_bfloat16 h, l;
    split2(src[i], h, l);
    hi[i] = h; lo[i] = l;
}

// ---------------------------------------------------------------------------
// Embedding gather + positional encoding -> g_x
// ---------------------------------------------------------------------------
__global__ void embed_kernel(const int* __restrict__ tokens,
                             const float* __restrict__ emb)
{
    int idx = blockIdx.x * blockDim.x + threadIdx.x;
    if (idx >= BTq * Dq) return;
    int d  = idx & (Dq - 1);
    int bt = idx >> 9;
    int t  = bt & (Tq - 1);
    int tok = tokens[bt];
    float div = expf((float)(d & ~1) * (-9.210340371976184f / (float)Dq));
    float ang = (float)t * div;
    float pe  = (d & 1) ? cosf(ang) : sinf(ang);
    g_x[idx] = emb[(size_t)tok * Dq + d] + pe;
}

// ---------------------------------------------------------------------------
// Fused LN1 -> cos -> head-Gram attention -> hi/lo split output
// ---------------------------------------------------------------------------
__global__ __launch_bounds__(256)
void attn_kernel(const float* __restrict__ xin,
                 const float* __restrict__ lns,
                 const float* __restrict__ lnb,
                 const float* __restrict__ rx_sum_p,
                 __nv_bfloat16* __restrict__ oh,
                 __nv_bfloat16* __restrict__ ol)
{
    int row = blockIdx.x;
    const float* xr = xin + (size_t)row * Dq;
    int tid = threadIdx.x;

    float v0 = xr[tid];
    float v1 = xr[tid + 256];
    float sum = v0 + v1;
    float sq  = v0 * v0 + v1 * v1;
    #pragma unroll
    for (int o = 16; o; o >>= 1) {
        sum += __shfl_xor_sync(0xFFFFFFFFu, sum, o);
        sq  += __shfl_xor_sync(0xFFFFFFFFu, sq,  o);
    }
    __shared__ float wsum[8], wsq[8];
    int wid = tid >> 5, lid = tid & 31;
    if (lid == 0) { wsum[wid] = sum; wsq[wid] = sq; }
    __syncthreads();
    if (tid == 0) {
        float s = 0.f, q2 = 0.f;
        #pragma unroll
        for (int i = 0; i < 8; i++) { s += wsum[i]; q2 += wsq[i]; }
        wsum[0] = s; wsq[0] = q2;
    }
    __syncthreads();
    float mu  = wsum[0] * (1.0f / Dq);
    float var = wsq[0] * (1.0f / Dq) - mu * mu;
    float rs  = rsqrtf(var + 1e-5f);
    float rxs = *rx_sum_p;

    __shared__ float q[Dq];
    q[tid]       = cosf((v0 - mu) * rs * lns[tid]       + lnb[tid]       + rxs);
    q[tid + 256] = cosf((v1 - mu) * rs * lns[tid + 256] + lnb[tid + 256] + rxs);
    __syncthreads();

    int h = tid >> 4, g = tid & 15;
    const float* qh_ = q + h * HDq;
    const float* qg_ = q + g * HDq;
    float sc = 0.f;
    #pragma unroll
    for (int d = 0; d < HDq; d++) sc += qh_[d] * qg_[d];
    sc *= 0.17677669529663687f;

    float mx = sc;
    #pragma unroll
    for (int o = 8; o; o >>= 1) mx = fmaxf(mx, __shfl_xor_sync(0xFFFFFFFFu, mx, o));
    float e = expf(sc - mx);
    float se = e;
    #pragma unroll
    for (int o = 8; o; o >>= 1) se += __shfl_xor_sync(0xFFFFFFFFu, se, o);

    __shared__ float a[Hq * Hq];
    a[tid] = e / se;
    __syncthreads();

    int h0 = tid >> 5, d0 = tid & 31;
    int h1 = (tid + 256) >> 5;
    float o0 = 0.f, o1 = 0.f;
    #pragma unroll
    for (int gg = 0; gg < Hq; gg++) {
        float qv = q[gg * HDq + d0];
        o0 += a[h0 * Hq + gg] * qv;
        o1 += a[h1 * Hq + gg] * qv;
    }
    __nv_bfloat16 hh, ll;
    split2(o0, hh, ll);
    oh[(size_t)row * Dq + tid] = hh;  ol[(size_t)row * Dq + tid] = ll;
    split2(o1, hh, ll);
    oh[(size_t)row * Dq + tid + 256] = hh;  ol[(size_t)row * Dq + tid + 256] = ll;
}

// ---------------------------------------------------------------------------
// Fused LN2 -> ry_cos * cos -> hi/lo split output
// ---------------------------------------------------------------------------
__global__ __launch_bounds__(256)
void ffact_kernel(const float* __restrict__ xin,
                  const float* __restrict__ lns,
                  const float* __restrict__ lnb,
                  const float* __restrict__ ry_cos_p,
                  __nv_bfloat16* __restrict__ oh,
                  __nv_bfloat16* __restrict__ ol)
{
    int row = blockIdx.x;
    const float* xr = xin + (size_t)row * Dq;
    int tid = threadIdx.x;

    float v0 = xr[tid];
    float v1 = xr[tid + 256];
    float sum = v0 + v1;
    float sq  = v0 * v0 + v1 * v1;
    #pragma unroll
    for (int o = 16; o; o >>= 1) {
        sum += __shfl_xor_sync(0xFFFFFFFFu, sum, o);
        sq  += __shfl_xor_sync(0xFFFFFFFFu, sq,  o);
    }
    __shared__ float wsum[8], wsq[8];
    int wid = tid >> 5, lid = tid & 31;
    if (lid == 0) { wsum[wid] = sum; wsq[wid] = sq; }
    __syncthreads();
    if (tid == 0) {
        float s = 0.f, q2 = 0.f;
        #pragma unroll
        for (int i = 0; i < 8; i++) { s += wsum[i]; q2 += wsq[i]; }
        wsum[0] = s; wsq[0] = q2;
    }
    __syncthreads();
    float mu  = wsum[0] * (1.0f / Dq);
    float var = wsq[0] * (1.0f / Dq) - mu * mu;
    float rs  = rsqrtf(var + 1e-5f);
    float ryc = *ry_cos_p;

    size_t base = (size_t)row * Dq;
    __nv_bfloat16 hh, ll;
    float a0 = ryc * cosf((v0 - mu) * rs * lns[tid]       + lnb[tid]);
    float a1 = ryc * cosf((v1 - mu) * rs * lns[tid + 256] + lnb[tid + 256]);
    split2(a0, hh, ll); oh[base + tid] = hh;       ol[base + tid] = ll;
    split2(a1, hh, ll); oh[base + tid + 256] = hh; ol[base + tid + 256] = ll;
}

// ---------------------------------------------------------------------------
// Pooling: phase 1 partial sums, phase 2 classifier
// ---------------------------------------------------------------------------
__global__ __launch_bounds__(512)
void pool_partial_kernel()
{
    int chunk = blockIdx.x;      // 0..15
    int b     = blockIdx.y;      // 0..15
    int d     = threadIdx.x;     // 0..511
    const float* xb = g_x + ((size_t)b * Tq + chunk * 128) * Dq + d;
    float s = 0.f;
    #pragma unroll 4
    for (int t = 0; t < 128; ++t) s += xb[(size_t)t * Dq];
    g_pp[((size_t)b * 16 + chunk) * Dq + d] = s;
}

__global__ __launch_bounds__(512)
void clf_kernel(const float* __restrict__ clf_w,
                const float* __restrict__ clf_b,
                float* __restrict__ out)
{
    int b = blockIdx.x;
    int tid = threadIdx.x;
    __shared__ float pooled[Dq];
    float s = 0.f;
    #pragma unroll
    for (int c = 0; c < 16; ++c) s += g_pp[((size_t)b * 16 + c) * Dq + tid];
    pooled[tid] = s * (1.0f / Tq);
    __syncthreads();
    if (tid < Cq) {
        float acc = clf_b[tid];
        const float* wr = clf_w + (size_t)tid * Dq;
        for (int d = 0; d < Dq; d++) acc += pooled[d] * wr[d];
        out[b * Cq + tid] = acc;
    }
}

// ---------------------------------------------------------------------------
// Launch
// ---------------------------------------------------------------------------
extern "C" void kernel_launch(void* const* d_in, const int* in_sizes, int n_in,
                              void* d_out, int out_size)
{
    (void)in_sizes; (void)n_in; (void)out_size;

    const int*   tokens = (const int*)  d_in[0];
    const float* emb    = (const float*)d_in[1];
    const float* ln1_s  = (const float*)d_in[2];
    const float* ln1_b  = (const float*)d_in[3];
    const float* ln2_s  = (const float*)d_in[4];
    const float* ln2_b  = (const float*)d_in[5];
    const float* rx     = (const float*)d_in[6];
    const float* ry     = (const float*)d_in[7];
    const float* proj_w = (const float*)d_in[8];
    const float* lin1_w = (const float*)d_in[9];
    const float* lin2_w = (const float*)d_in[10];
    const float* clf_w  = (const float*)d_in[11];
    const float* clf_b  = (const float*)d_in[12];
    float* out = (float*)d_out;

    float *px, *prx, *pryc;
    __nv_bfloat16 *pah, *pal, *pffh, *pffl;
    __nv_bfloat16 *pwph, *pwpl, *pw1h, *pw1l, *pw2h, *pw2l;
    cudaGetSymbolAddress((void**)&px,   g_x);
    cudaGetSymbolAddress((void**)&prx,  g_rx_sum);
    cudaGetSymbolAddress((void**)&pryc, g_ry_cos);
    cudaGetSymbolAddress((void**)&pah,  g_ah);
    cudaGetSymbolAddress((void**)&pal,  g_al);
    cudaGetSymbolAddress((void**)&pffh, g_ffh);
    cudaGetSymbolAddress((void**)&pffl, g_ffl);
    cudaGetSymbolAddress((void**)&pwph, g_wph);
    cudaGetSymbolAddress((void**)&pwpl, g_wpl);
    cudaGetSymbolAddress((void**)&pw1h, g_w1h);
    cudaGetSymbolAddress((void**)&pw1l, g_w1l);
    cudaGetSymbolAddress((void**)&pw2h, g_w2h);
    cudaGetSymbolAddress((void**)&pw2l, g_w2l);

    cudaFuncSetAttribute(gemm_mma<0>, cudaFuncAttributeMaxDynamicSharedMemorySize,
                         GEMM_SMEM_BYTES);
    cudaFuncSetAttribute(gemm_mma<1>, cudaFuncAttributeMaxDynamicSharedMemorySize,
                         GEMM_SMEM_BYTES);

    scalars_kernel<<<Lq, 512>>>(rx, ry);
    embed_kernel<<<(BTq * Dq + 255) / 256, 256>>>(tokens, emb);

    {
        int n1 = Lq * Dq * Dq, n2 = Lq * Fq * Dq, n3 = Lq * Dq * Fq;
        convert_kernel<<<(n1 + 255) / 256, 256>>>(proj_w, pwph, pwpl, n1);
        convert_kernel<<<(n2 + 255) / 256, 256>>>(lin1_w, pw1h, pw1l, n2);
        convert_kernel<<<(n3 + 255) / 256, 256>>>(lin2_w, pw2h, pw2l, n3);
    }

    for (int l = 0; l < Lq; l++) {
        attn_kernel<<<BTq, 256>>>(px, ln1_s + l * Dq, ln1_b + l * Dq,
                                  prx + l, pah, pal);
        gemm_mma<0><<<dim3(Dq / 128, BTq / 128), 256, GEMM_SMEM_BYTES>>>(
            pah, pal, pwph + (size_t)l * Dq * Dq, pwpl + (size_t)l * Dq * Dq,
            px, nullptr, nullptr, Dq, Dq);
        ffact_kernel<<<BTq, 256>>>(px, ln2_s + l * Dq, ln2_b + l * Dq,
                                   pryc + l, pah, pal);
        gemm_mma<1><<<dim3(Fq / 128, BTq / 128), 256, GEMM_SMEM_BYTES>>>(
            pah, pal, pw1h + (size_t)l * Fq * Dq, pw1l + (size_t)l * Fq * Dq,
            nullptr, pffh, pffl, Fq, Dq);
        gemm_mma<0><<<dim3(Dq / 128, BTq / 128), 256, GEMM_SMEM_BYTES>>>(
            pffh, pffl, pw2h + (size_t)l * Dq * Fq, pw2l + (size_t)l * Dq * Fq,
            px, nullptr, nullptr, Dq, Fq);
    }

    pool_partial_kernel<<<dim3(16, Bq), 512>>>();
    clf_kernel<<<Bq, 512>>>(clf_w, clf_b, out);
}

// round 4
// speedup vs baseline: 1.9558x; 1.0068x over previous
#include <cuda_runtime.h>
#include <cuda_bf16.h>
#include <math.h>
#include <stdint.h>

// Problem constants
#define Bq   16
#define Tq   2048
#define Dq   512
#define Hq   16
#define HDq  32
#define Fq   2048
#define Lq   4
#define Cq   10
#define BTq  (Bq * Tq)          // 32768 rows

// ---------------------------------------------------------------------------
// Static device scratch
// ---------------------------------------------------------------------------
__device__ float         g_x  [BTq * Dq];        // fp32 residual stream
__device__ __nv_bfloat16 g_ah [BTq * Dq];        // activation hi
__device__ __nv_bfloat16 g_al [BTq * Dq];        // activation lo
__device__ __nv_bfloat16 g_ffh[BTq * Fq];        // ffn intermediate hi
__device__ __nv_bfloat16 g_ffl[BTq * Fq];        // ffn intermediate lo
__device__ __nv_bfloat16 g_wph[Lq * Dq * Dq], g_wpl[Lq * Dq * Dq];
__device__ __nv_bfloat16 g_w1h[Lq * Fq * Dq], g_w1l[Lq * Fq * Dq];
__device__ __nv_bfloat16 g_w2h[Lq * Dq * Fq], g_w2l[Lq * Dq * Fq];
__device__ float         g_pp [Bq * 16 * Dq];    // pooling partials
__device__ float         g_rx_sum[Lq];
__device__ float         g_ry_cos[Lq];

// ---------------------------------------------------------------------------
// Helpers
// ---------------------------------------------------------------------------
__device__ __forceinline__ uint32_t smem_u32(const void* p) {
    uint32_t a;
    asm("{ .reg .u64 t; cvta.to.shared.u64 t, %1; cvt.u32.u64 %0, t; }"
        : "=r"(a) : "l"(p));
    return a;
}

__device__ __forceinline__ void cp_async16(uint32_t dst, const void* src) {
    asm volatile("cp.async.cg.shared.global [%0], [%1], 16;"
                 :: "r"(dst), "l"(src) : "memory");
}
#define CP_COMMIT()  asm volatile("cp.async.commit_group;" ::: "memory")
#define CP_WAIT(n)   asm volatile("cp.async.wait_group %0;" :: "n"(n) : "memory")

__device__ __forceinline__ void ldsm4(uint32_t* r, uint32_t addr) {
    asm volatile("ldmatrix.sync.aligned.m8n8.x4.shared.b16 {%0,%1,%2,%3}, [%4];"
                 : "=r"(r[0]), "=r"(r[1]), "=r"(r[2]), "=r"(r[3]) : "r"(addr));
}

__device__ __forceinline__ void mma16816(float* d, const uint32_t* a,
                                         const uint32_t* b) {
    asm volatile(
        "mma.sync.aligned.m16n8k16.row.col.f32.bf16.bf16.f32 "
        "{%0,%1,%2,%3}, {%4,%5,%6,%7}, {%8,%9}, {%0,%1,%2,%3};"
        : "+f"(d[0]), "+f"(d[1]), "+f"(d[2]), "+f"(d[3])
        : "r"(a[0]), "r"(a[1]), "r"(a[2]), "r"(a[3]), "r"(b[0]), "r"(b[1]));
}

__device__ __forceinline__ void split2(float v, __nv_bfloat16& h, __nv_bfloat16& l) {
    h = __float2bfloat16(v);
    l = __float2bfloat16(v - __bfloat162float(h));
}

// ---------------------------------------------------------------------------
// Split-bf16 tensor-core GEMM (mma.sync):
//   C[m,n] = sum_k A[m,k] * B[n,k],   A = Ah+Al, B = Bh+Bl (bf16 hi/lo)
//   D = Ah*Bh + Ah*Bl + Al*Bh  (fp32 accum, ~2^-18 accurate)
// CTA tile 128x128, BK=32, 256 threads (4 m-warps x 2 n-warps, 32x64 per warp)
// 3-stage cp.async pipeline. SMEM rows padded to 80B (conflict-free ldmatrix).
// EPI 0: C += D (fp32 residual).  EPI 1: relu(D) -> split -> (Oh, Ol).
// ---------------------------------------------------------------------------
#define TILE_B   10240              // 128 rows * 80 bytes
#define STAGE_B  (4 * TILE_B)       // Ah, Al, Bh, Bl
#define GEMM_SMEM_BYTES (3 * STAGE_B)

template <int EPI>
__global__ __launch_bounds__(256, 1)
void gemm_mma(const __nv_bfloat16* __restrict__ Ah, const __nv_bfloat16* __restrict__ Al,
              const __nv_bfloat16* __restrict__ Bh, const __nv_bfloat16* __restrict__ Bl,
              float* __restrict__ C,
              __nv_bfloat16* __restrict__ Oh, __nv_bfloat16* __restrict__ Ol,
              int N, int K)
{
    extern __shared__ char smem[];
    const uint32_t sbase = smem_u32(smem);
    const int tid  = threadIdx.x;
    const int wid  = tid >> 5;
    const int lane = tid & 31;
    const int wm   = wid & 3;          // m-warp: rows wm*32 .. +31
    const int wn   = wid >> 2;         // n-warp: cols wn*64 .. +63

    const int bm = blockIdx.y * 128;
    const int bn = blockIdx.x * 128;

    const __nv_bfloat16* gsrc[4] = { Ah, Al, Bh, Bl };
    const int rowbase[4] = { bm, bm, bn, bn };

    // stage loader: 4 tiles x 128 rows x 32 bf16; 16B per cp.async
    auto load_stage = [&](int s, int kiter) {
        const uint32_t st = sbase + s * STAGE_B;
        #pragma unroll
        for (int t = 0; t < 4; ++t) {
            #pragma unroll
            for (int half = 0; half < 2; ++half) {
                int idx = tid + half * 256;      // 0..511
                int row = idx >> 2;
                int c   = idx & 3;
                const __nv_bfloat16* src =
                    gsrc[t] + (size_t)(rowbase[t] + row) * K + kiter * 32 + c * 8;
                cp_async16(st + t * TILE_B + row * 80 + c * 16, src);
            }
        }
    };

    float acc[2][8][4];
    #pragma unroll
    for (int i = 0; i < 2; ++i)
        #pragma unroll
        for (int j = 0; j < 8; ++j)
            #pragma unroll
            for (int k = 0; k < 4; ++k) acc[i][j][k] = 0.f;

    const int nc = K >> 5;             // K / 32

    load_stage(0, 0); CP_COMMIT();
    load_stage(1, 1); CP_COMMIT();

    const uint32_t lrow16 = (uint32_t)(lane & 15) * 80;   // row within frag
    const uint32_t khalf  = (uint32_t)(lane >> 4) * 16;   // k-half 16B

    for (int i = 0; i < nc; ++i) {
        CP_WAIT(1);
        __syncthreads();

        const uint32_t st = sbase + (uint32_t)(i % 3) * STAGE_B;
        #pragma unroll
        for (int ks = 0; ks < 2; ++ks) {
            const uint32_t kb = ks * 32 + khalf;

            uint32_t a_h[2][4], a_l[2][4];
            #pragma unroll
            for (int mf = 0; mf < 2; ++mf) {
                uint32_t ad = st + (uint32_t)(wm * 32 + mf * 16) * 80 + lrow16 + kb;
                ldsm4(a_h[mf], ad);
                ldsm4(a_l[mf], ad + TILE_B);
            }
            uint32_t b_h[8][2], b_l[8][2];
            #pragma unroll
            for (int nq = 0; nq < 4; ++nq) {
                uint32_t bd = st + 2 * TILE_B +
                              (uint32_t)(wn * 64 + nq * 16) * 80 + lrow16 + kb;
                uint32_t r[4];
                ldsm4(r, bd);
                b_h[nq * 2][0] = r[0]; b_h[nq * 2][1] = r[2];
                b_h[nq * 2 + 1][0] = r[1]; b_h[nq * 2 + 1][1] = r[3];
                ldsm4(r, bd + TILE_B);
                b_l[nq * 2][0] = r[0]; b_l[nq * 2][1] = r[2];
                b_l[nq * 2 + 1][0] = r[1]; b_l[nq * 2 + 1][1] = r[3];
            }
            #pragma unroll
            for (int mf = 0; mf < 2; ++mf)
                #pragma unroll
                for (int nf = 0; nf < 8; ++nf) {
                    mma16816(acc[mf][nf], a_h[mf], b_h[nf]);
                    mma16816(acc[mf][nf], a_h[mf], b_l[nf]);
                    mma16816(acc[mf][nf], a_l[mf], b_h[nf]);
                }
        }

        if (i + 2 < nc) load_stage((i + 2) % 3, i + 2);
        CP_COMMIT();
    }

    // epilogue: thread owns rows r0, r0+8; cols col, col+1 per (mf, nf)
    #pragma unroll
    for (int mf = 0; mf < 2; ++mf) {
        const int r0 = bm + wm * 32 + mf * 16 + (lane >> 2);
        #pragma unroll
        for (int nf = 0; nf < 8; ++nf) {
            const int col = bn + wn * 64 + nf * 8 + (lane & 3) * 2;
            float* d = acc[mf][nf];
            if (EPI == 0) {
                float* c0 = C + (size_t)r0 * N + col;
                float* c1 = C + (size_t)(r0 + 8) * N + col;
                c0[0] += d[0]; c0[1] += d[1];
                c1[0] += d[2]; c1[1] += d[3];
            } else {
                #pragma unroll
                for (int rr = 0; rr < 2; ++rr) {
                    size_t off = (size_t)(r0 + rr * 8) * N + col;
                    float v0 = fmaxf(d[rr * 2 + 0], 0.f);
                    float v1 = fmaxf(d[rr * 2 + 1], 0.f);
                    __nv_bfloat16 h0, l0, h1, l1;
                    split2(v0, h0, l0);
                    split2(v1, h1, l1);
                    *(__nv_bfloat162*)(Oh + off) = __nv_bfloat162(h0, h1);
                    *(__nv_bfloat162*)(Ol + off) = __nv_bfloat162(l0, l1);
                }
            }
        }
    }
}

// ---------------------------------------------------------------------------
// Per-layer scalar reductions
// ---------------------------------------------------------------------------
__global__ void scalars_kernel(const float* __restrict__ rx,
                               const float* __restrict__ ry)
{
    int l = blockIdx.x;
    __shared__ float red[512];
    int tid = threadIdx.x;
    red[tid] = ry[l * Dq + tid];
    __syncthreads();
    for (int s = 256; s; s >>= 1) {
        if (tid < s) red[tid] += red[tid + s];
        __syncthreads();
    }
    if (tid == 0) {
        g_ry_cos[l] = cosf(red[0]);
        float s = 0.f;
        #pragma unroll
        for (int i = 0; i < HDq; i++) s += rx[l * HDq + i];
        g_rx_sum[l] = s;
    }
}

// ---------------------------------------------------------------------------
// Weight hi/lo split conversion
// ---------------------------------------------------------------------------
__global__ void convert_kernel(const float* __restrict__ src,
                               __nv_bfloat16* __restrict__ hi,
                               __nv_bfloat16* __restrict__ lo, int n)
{
    int i = blockIdx.x * blockDim.x + threadIdx.x;
    if (i >= n) return;
    __nv_bfloat16 h, l;
    split2(src[i], h, l);
    hi[i] = h; lo[i] = l;
}

// ---------------------------------------------------------------------------
// Embedding gather + positional encoding -> g_x
// ---------------------------------------------------------------------------
__global__ void embed_kernel(const int* __restrict__ tokens,
                             const float* __restrict__ emb)
{
    int idx = blockIdx.x * blockDim.x + threadIdx.x;
    if (idx >= BTq * Dq) return;
    int d  = idx & (Dq - 1);
    int bt = idx >> 9;
    int t  = bt & (Tq - 1);
    int tok = tokens[bt];
    float div = expf((float)(d & ~1) * (-9.210340371976184f / (float)Dq));
    float ang = (float)t * div;
    float pe  = (d & 1) ? cosf(ang) : sinf(ang);
    g_x[idx] = emb[(size_t)tok * Dq + d] + pe;
}

// ---------------------------------------------------------------------------
// Fused LN1 -> cos -> head-Gram attention -> hi/lo split output
// ---------------------------------------------------------------------------
__global__ __launch_bounds__(256)
void attn_kernel(const float* __restrict__ xin,
                 const float* __restrict__ lns,
                 const float* __restrict__ lnb,
                 const float* __restrict__ rx_sum_p,
                 __nv_bfloat16* __restrict__ oh,
                 __nv_bfloat16* __restrict__ ol)
{
    int row = blockIdx.x;
    const float* xr = xin + (size_t)row * Dq;
    int tid = threadIdx.x;

    float v0 = xr[tid];
    float v1 = xr[tid + 256];
    float sum = v0 + v1;
    float sq  = v0 * v0 + v1 * v1;
    #pragma unroll
    for (int o = 16; o; o >>= 1) {
        sum += __shfl_xor_sync(0xFFFFFFFFu, sum, o);
        sq  += __shfl_xor_sync(0xFFFFFFFFu, sq,  o);
    }
    __shared__ float wsum[8], wsq[8];
    int wid = tid >> 5, lid = tid & 31;
    if (lid == 0) { wsum[wid] = sum; wsq[wid] = sq; }
    __syncthreads();
    if (tid == 0) {
        float s = 0.f, q2 = 0.f;
        #pragma unroll
        for (int i = 0; i < 8; i++) { s += wsum[i]; q2 += wsq[i]; }
        wsum[0] = s; wsq[0] = q2;
    }
    __syncthreads();
    float mu  = wsum[0] * (1.0f / Dq);
    float var = wsq[0] * (1.0f / Dq) - mu * mu;
    float rs  = rsqrtf(var + 1e-5f);
    float rxs = *rx_sum_p;

    __shared__ float q[Dq];
    q[tid]       = cosf((v0 - mu) * rs * lns[tid]       + lnb[tid]       + rxs);
    q[tid + 256] = cosf((v1 - mu) * rs * lns[tid + 256] + lnb[tid + 256] + rxs);
    __syncthreads();

    int h = tid >> 4, g = tid & 15;
    const float* qh_ = q + h * HDq;
    const float* qg_ = q + g * HDq;
    float sc = 0.f;
    #pragma unroll
    for (int d = 0; d < HDq; d++) sc += qh_[d] * qg_[d];
    sc *= 0.17677669529663687f;

    float mx = sc;
    #pragma unroll
    for (int o = 8; o; o >>= 1) mx = fmaxf(mx, __shfl_xor_sync(0xFFFFFFFFu, mx, o));
    float e = expf(sc - mx);
    float se = e;
    #pragma unroll
    for (int o = 8; o; o >>= 1) se += __shfl_xor_sync(0xFFFFFFFFu, se, o);

    __shared__ float a[Hq * Hq];
    a[tid] = e / se;
    __syncthreads();

    int h0 = tid >> 5, d0 = tid & 31;
    int h1 = (tid + 256) >> 5;
    float o0 = 0.f, o1 = 0.f;
    #pragma unroll
    for (int gg = 0; gg < Hq; gg++) {
        float qv = q[gg * HDq + d0];
        o0 += a[h0 * Hq + gg] * qv;
        o1 += a[h1 * Hq + gg] * qv;
    }
    __nv_bfloat16 hh, ll;
    split2(o0, hh, ll);
    oh[(size_t)row * Dq + tid] = hh;  ol[(size_t)row * Dq + tid] = ll;
    split2(o1, hh, ll);
    oh[(size_t)row * Dq + tid + 256] = hh;  ol[(size_t)row * Dq + tid + 256] = ll;
}

// ---------------------------------------------------------------------------
// Fused LN2 -> ry_cos * cos -> hi/lo split output
// ---------------------------------------------------------------------------
__global__ __launch_bounds__(256)
void ffact_kernel(const float* __restrict__ xin,
                  const float* __restrict__ lns,
                  const float* __restrict__ lnb,
                  const float* __restrict__ ry_cos_p,
                  __nv_bfloat16* __restrict__ oh,
                  __nv_bfloat16* __restrict__ ol)
{
    int row = blockIdx.x;
    const float* xr = xin + (size_t)row * Dq;
    int tid = threadIdx.x;

    float v0 = xr[tid];
    float v1 = xr[tid + 256];
    float sum = v0 + v1;
    float sq  = v0 * v0 + v1 * v1;
    #pragma unroll
    for (int o = 16; o; o >>= 1) {
        sum += __shfl_xor_sync(0xFFFFFFFFu, sum, o);
        sq  += __shfl_xor_sync(0xFFFFFFFFu, sq,  o);
    }
    __shared__ float wsum[8], wsq[8];
    int wid = tid >> 5, lid = tid & 31;
    if (lid == 0) { wsum[wid] = sum; wsq[wid] = sq; }
    __syncthreads();
    if (tid == 0) {
        float s = 0.f, q2 = 0.f;
        #pragma unroll
        for (int i = 0; i < 8; i++) { s += wsum[i]; q2 += wsq[i]; }
        wsum[0] = s; wsq[0] = q2;
    }
    __syncthreads();
    float mu  = wsum[0] * (1.0f / Dq);
    float var = wsq[0] * (1.0f / Dq) - mu * mu;
    float rs  = rsqrtf(var + 1e-5f);
    float ryc = *ry_cos_p;

    size_t base = (size_t)row * Dq;
    __nv_bfloat16 hh, ll;
    float a0 = ryc * cosf((v0 - mu) * rs * lns[tid]       + lnb[tid]);
    float a1 = ryc * cosf((v1 - mu) * rs * lns[tid + 256] + lnb[tid + 256]);
    split2(a0, hh, ll); oh[base + tid] = hh;       ol[base + tid] = ll;
    split2(a1, hh, ll); oh[base + tid + 256] = hh; ol[base + tid + 256] = ll;
}

// ---------------------------------------------------------------------------
// Pooling: phase 1 partial sums, phase 2 classifier
// ---------------------------------------------------------------------------
__global__ __launch_bounds__(512)
void pool_partial_kernel()
{
    int chunk = blockIdx.x;      // 0..15
    int b     = blockIdx.y;      // 0..15
    int d     = threadIdx.x;     // 0..511
    const float* xb = g_x + ((size_t)b * Tq + chunk * 128) * Dq + d;
    float s = 0.f;
    #pragma unroll 4
    for (int t = 0; t < 128; ++t) s += xb[(size_t)t * Dq];
    g_pp[((size_t)b * 16 + chunk) * Dq + d] = s;
}

__global__ __launch_bounds__(512)
void clf_kernel(const float* __restrict__ clf_w,
                const float* __restrict__ clf_b,
                float* __restrict__ out)
{
    int b = blockIdx.x;
    int tid = threadIdx.x;
    __shared__ float pooled[Dq];
    float s = 0.f;
    #pragma unroll
    for (int c = 0; c < 16; ++c) s += g_pp[((size_t)b * 16 + c) * Dq + tid];
    pooled[tid] = s * (1.0f / Tq);
    __syncthreads();
    if (tid < Cq) {
        float acc = clf_b[tid];
        const float* wr = clf_w + (size_t)tid * Dq;
        for (int d = 0; d < Dq; d++) acc += pooled[d] * wr[d];
        out[b * Cq + tid] = acc;
    }
}

// ---------------------------------------------------------------------------
// Launch
// ---------------------------------------------------------------------------
extern "C" void kernel_launch(void* const* d_in, const int* in_sizes, int n_in,
                              void* d_out, int out_size)
{
    (void)in_sizes; (void)n_in; (void)out_size;

    const int*   tokens = (const int*)  d_in[0];
    const float* emb    = (const float*)d_in[1];
    const float* ln1_s  = (const float*)d_in[2];
    const float* ln1_b  = (const float*)d_in[3];
    const float* ln2_s  = (const float*)d_in[4];
    const float* ln2_b  = (const float*)d_in[5];
    const float* rx     = (const float*)d_in[6];
    const float* ry     = (const float*)d_in[7];
    const float* proj_w = (const float*)d_in[8];
    const float* lin1_w = (const float*)d_in[9];
    const float* lin2_w = (const float*)d_in[10];
    const float* clf_w  = (const float*)d_in[11];
    const float* clf_b  = (const float*)d_in[12];
    float* out = (float*)d_out;

    float *px, *prx, *pryc;
    __nv_bfloat16 *pah, *pal, *pffh, *pffl;
    __nv_bfloat16 *pwph, *pwpl, *pw1h, *pw1l, *pw2h, *pw2l;
    cudaGetSymbolAddress((void**)&px,   g_x);
    cudaGetSymbolAddress((void**)&prx,  g_rx_sum);
    cudaGetSymbolAddress((void**)&pryc, g_ry_cos);
    cudaGetSymbolAddress((void**)&pah,  g_ah);
    cudaGetSymbolAddress((void**)&pal,  g_al);
    cudaGetSymbolAddress((void**)&pffh, g_ffh);
    cudaGetSymbolAddress((void**)&pffl, g_ffl);
    cudaGetSymbolAddress((void**)&pwph, g_wph);
    cudaGetSymbolAddress((void**)&pwpl, g_wpl);
    cudaGetSymbolAddress((void**)&pw1h, g_w1h);
    cudaGetSymbolAddress((void**)&pw1l, g_w1l);
    cudaGetSymbolAddress((void**)&pw2h, g_w2h);
    cudaGetSymbolAddress((void**)&pw2l, g_w2l);

    cudaFuncSetAttribute(gemm_mma<0>, cudaFuncAttributeMaxDynamicSharedMemorySize,
                         GEMM_SMEM_BYTES);
    cudaFuncSetAttribute(gemm_mma<1>, cudaFuncAttributeMaxDynamicSharedMemorySize,
                         GEMM_SMEM_BYTES);

    scalars_kernel<<<Lq, 512>>>(rx, ry);
    embed_kernel<<<(BTq * Dq + 255) / 256, 256>>>(tokens, emb);

    {
        int n1 = Lq * Dq * Dq, n2 = Lq * Fq * Dq, n3 = Lq * Dq * Fq;
        convert_kernel<<<(n1 + 255) / 256, 256>>>(proj_w, pwph, pwpl, n1);
        convert_kernel<<<(n2 + 255) / 256, 256>>>(lin1_w, pw1h, pw1l, n2);
        convert_kernel<<<(n3 + 255) / 256, 256>>>(lin2_w, pw2h, pw2l, n3);
    }

    for (int l = 0; l < Lq; l++) {
        attn_kernel<<<BTq, 256>>>(px, ln1_s + l * Dq, ln1_b + l * Dq,
                                  prx + l, pah, pal);
        gemm_mma<0><<<dim3(Dq / 128, BTq / 128), 256, GEMM_SMEM_BYTES>>>(
            pah, pal, pwph + (size_t)l * Dq * Dq, pwpl + (size_t)l * Dq * Dq,
            px, nullptr, nullptr, Dq, Dq);
        ffact_kernel<<<BTq, 256>>>(px, ln2_s + l * Dq, ln2_b + l * Dq,
                                   pryc + l, pah, pal);
        gemm_mma<1><<<dim3(Fq / 128, BTq / 128), 256, GEMM_SMEM_BYTES>>>(
            pah, pal, pw1h + (size_t)l * Fq * Dq, pw1l + (size_t)l * Fq * Dq,
            nullptr, pffh, pffl, Fq, Dq);
        gemm_mma<0><<<dim3(Dq / 128, BTq / 128), 256, GEMM_SMEM_BYTES>>>(
            pffh, pffl, pw2h + (size_t)l * Dq * Fq, pw2l + (size_t)l * Dq * Fq,
            px, nullptr, nullptr, Dq, Fq);
    }

    pool_partial_kernel<<<dim3(16, Bq), 512>>>();
    clf_kernel<<<Bq, 512>>>(clf_w, clf_b, out);
}